// round 1
// baseline (speedup 1.0000x reference)
#include <cuda_runtime.h>

#define BSZ  4
#define CH   128
#define HID  256
#define OUTD 64
#define EPSV 1e-5f

__global__ __launch_bounds__(256, 1)
void proj_pyramid_kernel(const float* __restrict__ x0,
                         const float* __restrict__ x1,
                         const float* __restrict__ x2,
                         const float* __restrict__ x3,
                         const float* __restrict__ x4,
                         const int*   __restrict__ p,
                         const float* __restrict__ w1,
                         const float* __restrict__ b1,
                         const float* __restrict__ gamma,
                         const float* __restrict__ beta,
                         const float* __restrict__ w2,
                         const float* __restrict__ b2,
                         float*       __restrict__ out)
{
    const int k   = blockIdx.x;      // pyramid level 0..4
    const int tid = threadIdx.x;     // 0..255

    __shared__ float f_s[BSZ][CH];    // gathered features
    __shared__ float r_s[BSZ][HID];   // post-ReLU hidden

    const float* xs;
    switch (k) {
        case 0: xs = x0; break;
        case 1: xs = x1; break;
        case 2: xs = x2; break;
        case 3: xs = x3; break;
        default: xs = x4; break;
    }
    const int shift = k + 1;
    const int side  = 128 >> shift;

    // ---- Phase 0: gather (BSZ*CH = 512 scattered loads, 2 per thread) ----
    #pragma unroll
    for (int i = tid; i < BSZ * CH; i += 256) {
        const int b = i >> 7;        // / CH
        const int c = i & (CH - 1);
        const int q0 = p[b * 3 + 0] >> shift;
        const int q1 = p[b * 3 + 1] >> shift;
        const int q2 = p[b * 3 + 2] >> shift;
        const long long idx =
            ((((long long)(b * CH + c) * side + q0) * side + q1) * side + q2);
        f_s[b][c] = xs[idx];
    }
    __syncthreads();

    // ---- Phase 1: h = f @ W1^T + b1 ; BN(train, batch axis) ; ReLU ----
    // Thread tid owns hidden unit j = tid for ALL 4 batch rows -> BN stats local.
    {
        const int j = tid;
        const float4* w1row =
            (const float4*)(w1 + ((long long)k * HID + j) * CH);
        float a0 = 0.f, a1 = 0.f, a2 = 0.f, a3 = 0.f;
        #pragma unroll
        for (int c4 = 0; c4 < CH / 4; ++c4) {
            const float4 w = w1row[c4];
            const int c = c4 * 4;
            a0 += f_s[0][c] * w.x + f_s[0][c+1] * w.y + f_s[0][c+2] * w.z + f_s[0][c+3] * w.w;
            a1 += f_s[1][c] * w.x + f_s[1][c+1] * w.y + f_s[1][c+2] * w.z + f_s[1][c+3] * w.w;
            a2 += f_s[2][c] * w.x + f_s[2][c+1] * w.y + f_s[2][c+2] * w.z + f_s[2][c+3] * w.w;
            a3 += f_s[3][c] * w.x + f_s[3][c+1] * w.y + f_s[3][c+2] * w.z + f_s[3][c+3] * w.w;
        }
        const float bias = b1[k * HID + j];
        a0 += bias; a1 += bias; a2 += bias; a3 += bias;

        const float mean = 0.25f * (a0 + a1 + a2 + a3);
        const float d0 = a0 - mean, d1 = a1 - mean, d2 = a2 - mean, d3 = a3 - mean;
        const float var  = 0.25f * (d0*d0 + d1*d1 + d2*d2 + d3*d3);
        const float scl  = gamma[k * HID + j] * rsqrtf(var + EPSV);
        const float sh   = beta[k * HID + j];

        r_s[0][j] = fmaxf(d0 * scl + sh, 0.f);
        r_s[1][j] = fmaxf(d1 * scl + sh, 0.f);
        r_s[2][j] = fmaxf(d2 * scl + sh, 0.f);
        r_s[3][j] = fmaxf(d3 * scl + sh, 0.f);
    }
    __syncthreads();

    // ---- Phase 2: out = relu_h @ W2^T + b2 ----
    // thread t -> (b = t>>6, o = t&63); b is warp-uniform -> r_s reads broadcast.
    {
        const int b = tid >> 6;
        const int o = tid & (OUTD - 1);
        const float4* w2row =
            (const float4*)(w2 + ((long long)k * OUTD + o) * HID);
        const float4* rrow = (const float4*)(&r_s[b][0]);
        float acc = 0.f;
        #pragma unroll
        for (int j4 = 0; j4 < HID / 4; ++j4) {
            const float4 w = w2row[j4];
            const float4 r = rrow[j4];
            acc += r.x * w.x + r.y * w.y + r.z * w.z + r.w * w.w;
        }
        out[((long long)k * BSZ + b) * OUTD + o] = acc + b2[k * OUTD + o];
    }
}

extern "C" void kernel_launch(void* const* d_in, const int* in_sizes, int n_in,
                              void* d_out, int out_size)
{
    (void)in_sizes; (void)n_in; (void)out_size;
    const float* x0    = (const float*)d_in[0];
    const float* x1    = (const float*)d_in[1];
    const float* x2    = (const float*)d_in[2];
    const float* x3    = (const float*)d_in[3];
    const float* x4    = (const float*)d_in[4];
    const int*   p     = (const int*)  d_in[5];
    const float* w1    = (const float*)d_in[6];
    const float* b1    = (const float*)d_in[7];
    const float* gamma = (const float*)d_in[8];
    const float* beta  = (const float*)d_in[9];
    const float* w2    = (const float*)d_in[10];
    const float* b2    = (const float*)d_in[11];
    float* out = (float*)d_out;

    proj_pyramid_kernel<<<5, 256>>>(x0, x1, x2, x3, x4, p,
                                    w1, b1, gamma, beta, w2, b2, out);
}

// round 2
// speedup vs baseline: 1.2759x; 1.2759x over previous
#include <cuda_runtime.h>

#define BSZ  4
#define CH   128
#define HID  256
#define OUTD 64
#define EPSV 1e-5f

// scratch for post-ReLU hidden activations: [5][4][256]
__device__ float g_r[5 * BSZ * HID];

// ---------------------------------------------------------------------------
// Kernel A: gather + Conv1 + BN(train, batch axis) + ReLU -> g_r
// grid = 20 (level k = bx/4, j-chunk = bx%4), block = 256
// thread: jlocal = tid>>2 (0..63), cq = tid&3 (channel quarter: 32 ch)
// ---------------------------------------------------------------------------
__global__ __launch_bounds__(256, 1)
void proj_phase1_kernel(const float* __restrict__ x0,
                        const float* __restrict__ x1,
                        const float* __restrict__ x2,
                        const float* __restrict__ x3,
                        const float* __restrict__ x4,
                        const int*   __restrict__ p,
                        const float* __restrict__ w1,
                        const float* __restrict__ b1,
                        const float* __restrict__ gamma,
                        const float* __restrict__ beta)
{
    const int k     = blockIdx.x >> 2;
    const int jbase = (blockIdx.x & 3) * 64;
    const int tid   = threadIdx.x;

    __shared__ float f_s[BSZ][CH];

    const float* xs;
    switch (k) {
        case 0: xs = x0; break;
        case 1: xs = x1; break;
        case 2: xs = x2; break;
        case 3: xs = x3; break;
        default: xs = x4; break;
    }
    const int shift = k + 1;
    const int side  = 128 >> shift;

    // gather 512 scattered floats (2 per thread)
    #pragma unroll
    for (int i = tid; i < BSZ * CH; i += 256) {
        const int b = i >> 7;
        const int c = i & (CH - 1);
        const int q0 = p[b * 3 + 0] >> shift;
        const int q1 = p[b * 3 + 1] >> shift;
        const int q2 = p[b * 3 + 2] >> shift;
        const long long idx =
            ((((long long)(b * CH + c) * side + q0) * side + q1) * side + q2);
        f_s[b][c] = xs[idx];
    }
    __syncthreads();

    const int jloc = tid >> 2;          // hidden unit within chunk
    const int cq   = tid & 3;           // channel quarter
    const int j    = jbase + jloc;

    const float4* w1row =
        (const float4*)(w1 + ((long long)k * HID + j) * CH + cq * 32);
    const float4* f0 = (const float4*)(&f_s[0][cq * 32]);
    const float4* f1 = (const float4*)(&f_s[1][cq * 32]);
    const float4* f2 = (const float4*)(&f_s[2][cq * 32]);
    const float4* f3 = (const float4*)(&f_s[3][cq * 32]);

    float a0 = 0.f, a1 = 0.f, a2 = 0.f, a3 = 0.f;
    #pragma unroll
    for (int c4 = 0; c4 < 8; ++c4) {
        const float4 w  = w1row[c4];
        const float4 v0 = f0[c4];
        const float4 v1 = f1[c4];
        const float4 v2 = f2[c4];
        const float4 v3 = f3[c4];
        a0 += v0.x*w.x + v0.y*w.y + v0.z*w.z + v0.w*w.w;
        a1 += v1.x*w.x + v1.y*w.y + v1.z*w.z + v1.w*w.w;
        a2 += v2.x*w.x + v2.y*w.y + v2.z*w.z + v2.w*w.w;
        a3 += v3.x*w.x + v3.y*w.y + v3.z*w.z + v3.w*w.w;
    }
    // reduce across the 4 channel-quarter lanes (adjacent lanes in warp)
    a0 += __shfl_xor_sync(0xffffffffu, a0, 1);
    a1 += __shfl_xor_sync(0xffffffffu, a1, 1);
    a2 += __shfl_xor_sync(0xffffffffu, a2, 1);
    a3 += __shfl_xor_sync(0xffffffffu, a3, 1);
    a0 += __shfl_xor_sync(0xffffffffu, a0, 2);
    a1 += __shfl_xor_sync(0xffffffffu, a1, 2);
    a2 += __shfl_xor_sync(0xffffffffu, a2, 2);
    a3 += __shfl_xor_sync(0xffffffffu, a3, 2);

    if (cq == 0) {
        const float bias = b1[k * HID + j];
        a0 += bias; a1 += bias; a2 += bias; a3 += bias;

        const float mean = 0.25f * (a0 + a1 + a2 + a3);
        const float d0 = a0 - mean, d1 = a1 - mean, d2 = a2 - mean, d3 = a3 - mean;
        const float var  = 0.25f * (d0*d0 + d1*d1 + d2*d2 + d3*d3);
        const float scl  = gamma[k * HID + j] * rsqrtf(var + EPSV);
        const float sh   = beta[k * HID + j];

        float* rk = g_r + (long long)k * BSZ * HID;
        rk[0 * HID + j] = fmaxf(d0 * scl + sh, 0.f);
        rk[1 * HID + j] = fmaxf(d1 * scl + sh, 0.f);
        rk[2 * HID + j] = fmaxf(d2 * scl + sh, 0.f);
        rk[3 * HID + j] = fmaxf(d3 * scl + sh, 0.f);
    }
}

// ---------------------------------------------------------------------------
// Kernel B: out = relu_h @ W2^T + b2
// grid = 20 (level k = bx/4, batch b = bx%4), block = 256
// thread: o = tid>>2 (0..63), jq = tid&3 (64-channel quarter)
// ---------------------------------------------------------------------------
__global__ __launch_bounds__(256, 1)
void proj_phase2_kernel(const float* __restrict__ w2,
                        const float* __restrict__ b2,
                        float*       __restrict__ out)
{
    const int k = blockIdx.x >> 2;
    const int b = blockIdx.x & 3;
    const int tid = threadIdx.x;

    const int o  = tid >> 2;
    const int jq = tid & 3;

    const float4* rrow =
        (const float4*)(g_r + ((long long)(k * BSZ + b)) * HID + jq * 64);
    const float4* w2row =
        (const float4*)(w2 + ((long long)k * OUTD + o) * HID + jq * 64);

    float acc = 0.f;
    #pragma unroll
    for (int j4 = 0; j4 < 16; ++j4) {
        const float4 w = w2row[j4];
        const float4 r = rrow[j4];
        acc += r.x*w.x + r.y*w.y + r.z*w.z + r.w*w.w;
    }
    acc += __shfl_xor_sync(0xffffffffu, acc, 1);
    acc += __shfl_xor_sync(0xffffffffu, acc, 2);

    if (jq == 0)
        out[((long long)k * BSZ + b) * OUTD + o] = acc + b2[k * OUTD + o];
}

extern "C" void kernel_launch(void* const* d_in, const int* in_sizes, int n_in,
                              void* d_out, int out_size)
{
    (void)in_sizes; (void)n_in; (void)out_size;
    const float* x0    = (const float*)d_in[0];
    const float* x1    = (const float*)d_in[1];
    const float* x2    = (const float*)d_in[2];
    const float* x3    = (const float*)d_in[3];
    const float* x4    = (const float*)d_in[4];
    const int*   p     = (const int*)  d_in[5];
    const float* w1    = (const float*)d_in[6];
    const float* b1    = (const float*)d_in[7];
    const float* gamma = (const float*)d_in[8];
    const float* beta  = (const float*)d_in[9];
    const float* w2    = (const float*)d_in[10];
    const float* b2    = (const float*)d_in[11];
    float* out = (float*)d_out;

    proj_phase1_kernel<<<20, 256>>>(x0, x1, x2, x3, x4, p,
                                    w1, b1, gamma, beta);
    proj_phase2_kernel<<<20, 256>>>(w2, b2, out);
}

// round 3
// speedup vs baseline: 2.1143x; 1.6571x over previous
#include <cuda_runtime.h>

#define BSZ  4
#define CH   128
#define HID  256
#define OUTD 64
#define EPSV 1e-5f
#define ALLM 0xffffffffu

// scratch for post-ReLU hidden activations: [5][4][256]
__device__ float g_r[5 * BSZ * HID];

// ---------------------------------------------------------------------------
// Kernel A: gather + Conv1 + BN(train, batch axis) + ReLU -> g_r
// grid = 40 : k = bx>>3, j-chunk (32 units) = bx&7 ; block = 256
// thread: s = t&7 (interleaved channel eighth), j = chunk*32 + (t>>3)
// Warp-LDG of w1 touches 4 lines (coalesced); smem reads conflict-free.
// ---------------------------------------------------------------------------
__global__ __launch_bounds__(256, 1)
void proj_phase1_kernel(const float* __restrict__ x0,
                        const float* __restrict__ x1,
                        const float* __restrict__ x2,
                        const float* __restrict__ x3,
                        const float* __restrict__ x4,
                        const int*   __restrict__ p,
                        const float* __restrict__ w1,
                        const float* __restrict__ b1,
                        const float* __restrict__ gamma,
                        const float* __restrict__ beta)
{
    const int k   = blockIdx.x >> 3;
    const int jch = blockIdx.x & 7;
    const int t   = threadIdx.x;
    const int s   = t & 7;            // interleaved float4 slot
    const int j   = jch * 32 + (t >> 3);

    __shared__ float f_s[BSZ][CH];

    // ---- prefetch weights + BN params (independent of gather chain) ----
    const float4* wrow = (const float4*)(w1 + ((long long)k * HID + j) * CH);
    float4 wv[4];
    #pragma unroll
    for (int i = 0; i < 4; ++i)
        wv[i] = wrow[s + 8 * i];

    const float bias = b1[k * HID + j];
    const float gam  = gamma[k * HID + j];
    const float bet  = beta[k * HID + j];

    // ---- gather 512 scattered floats (2 per thread) ----
    const float* xs;
    switch (k) {
        case 0: xs = x0; break;
        case 1: xs = x1; break;
        case 2: xs = x2; break;
        case 3: xs = x3; break;
        default: xs = x4; break;
    }
    const int shift = k + 1;
    const int side  = 128 >> shift;

    #pragma unroll
    for (int i = t; i < BSZ * CH; i += 256) {
        const int b = i >> 7;
        const int c = i & (CH - 1);
        const int q0 = p[b * 3 + 0] >> shift;
        const int q1 = p[b * 3 + 1] >> shift;
        const int q2 = p[b * 3 + 2] >> shift;
        const long long idx =
            ((((long long)(b * CH + c) * side + q0) * side + q1) * side + q2);
        f_s[b][c] = xs[idx];
    }
    __syncthreads();

    // ---- partial dots: 16 channels (4 interleaved float4) x 4 batches ----
    const float4* f0 = (const float4*)f_s[0];
    const float4* f1 = (const float4*)f_s[1];
    const float4* f2 = (const float4*)f_s[2];
    const float4* f3 = (const float4*)f_s[3];

    float a0 = 0.f, a1 = 0.f, a2 = 0.f, a3 = 0.f;
    #pragma unroll
    for (int i = 0; i < 4; ++i) {
        const int fi = s + 8 * i;
        const float4 w  = wv[i];
        float4 v;
        v = f0[fi]; a0 += v.x*w.x + v.y*w.y + v.z*w.z + v.w*w.w;
        v = f1[fi]; a1 += v.x*w.x + v.y*w.y + v.z*w.z + v.w*w.w;
        v = f2[fi]; a2 += v.x*w.x + v.y*w.y + v.z*w.z + v.w*w.w;
        v = f3[fi]; a3 += v.x*w.x + v.y*w.y + v.z*w.z + v.w*w.w;
    }

    // ---- reduce across the 8 s-lanes (same j) ----
    #pragma unroll
    for (int m = 1; m < 8; m <<= 1) {
        a0 += __shfl_xor_sync(ALLM, a0, m);
        a1 += __shfl_xor_sync(ALLM, a1, m);
        a2 += __shfl_xor_sync(ALLM, a2, m);
        a3 += __shfl_xor_sync(ALLM, a3, m);
    }

    // ---- BN (batch stats are the 4 sums) + ReLU, lanes s=0..3 write b=s ----
    a0 += bias; a1 += bias; a2 += bias; a3 += bias;
    const float mean = 0.25f * (a0 + a1 + a2 + a3);
    const float d0 = a0 - mean, d1 = a1 - mean, d2 = a2 - mean, d3 = a3 - mean;
    const float var = 0.25f * (d0*d0 + d1*d1 + d2*d2 + d3*d3);
    const float scl = gam * rsqrtf(var + EPSV);

    if (s < 4) {
        const float d = (s == 0) ? d0 : (s == 1) ? d1 : (s == 2) ? d2 : d3;
        g_r[((long long)k * BSZ + s) * HID + j] = fmaxf(d * scl + bet, 0.f);
    }
}

// ---------------------------------------------------------------------------
// Kernel B: out = relu_h @ W2^T + b2
// grid = 40 : k = bx>>3, o-chunk (8 outs) = bx&7 ; block = 256
// thread: s = t&7 (interleaved slice), task T = t>>3 -> b = T&3, o = chunk*8 + T>>2
// Same-o lanes across b read identical w2 addresses (dedup); r reads coalesced.
// ---------------------------------------------------------------------------
__global__ __launch_bounds__(256, 1)
void proj_phase2_kernel(const float* __restrict__ w2,
                        const float* __restrict__ b2,
                        float*       __restrict__ out)
{
    const int k   = blockIdx.x >> 3;
    const int och = blockIdx.x & 7;
    const int t   = threadIdx.x;
    const int s   = t & 7;
    const int T   = t >> 3;            // 0..31
    const int b   = T & 3;
    const int o   = och * 8 + (T >> 2);

    const float4* wrow = (const float4*)(w2 + ((long long)k * OUTD + o) * HID);
    const float4* rrow = (const float4*)(g_r + ((long long)k * BSZ + b) * HID);

    float acc = 0.f;
    #pragma unroll
    for (int i = 0; i < 8; ++i) {
        const int fi = s + 8 * i;
        const float4 w = wrow[fi];
        const float4 r = rrow[fi];
        acc += r.x*w.x + r.y*w.y + r.z*w.z + r.w*w.w;
    }
    #pragma unroll
    for (int m = 1; m < 8; m <<= 1)
        acc += __shfl_xor_sync(ALLM, acc, m);

    if (s == 0)
        out[((long long)k * BSZ + b) * OUTD + o] = acc + b2[k * OUTD + o];
}

extern "C" void kernel_launch(void* const* d_in, const int* in_sizes, int n_in,
                              void* d_out, int out_size)
{
    (void)in_sizes; (void)n_in; (void)out_size;
    const float* x0    = (const float*)d_in[0];
    const float* x1    = (const float*)d_in[1];
    const float* x2    = (const float*)d_in[2];
    const float* x3    = (const float*)d_in[3];
    const float* x4    = (const float*)d_in[4];
    const int*   p     = (const int*)  d_in[5];
    const float* w1    = (const float*)d_in[6];
    const float* b1    = (const float*)d_in[7];
    const float* gamma = (const float*)d_in[8];
    const float* beta  = (const float*)d_in[9];
    const float* w2    = (const float*)d_in[10];
    const float* b2    = (const float*)d_in[11];
    float* out = (float*)d_out;

    proj_phase1_kernel<<<40, 256>>>(x0, x1, x2, x3, x4, p,
                                    w1, b1, gamma, beta);
    proj_phase2_kernel<<<40, 256>>>(w2, b2, out);
}

// round 4
// speedup vs baseline: 2.1845x; 1.0332x over previous
#include <cuda_runtime.h>

#define BSZ  4
#define CH   128
#define HID  256
#define OUTD 64
#define EPSV 1e-5f
#define ALLM 0xffffffffu

// scratch for post-ReLU hidden activations: [5][4][256]
__device__ float g_r[5 * BSZ * HID];
// per-level arrival counters (zero-init at module load; reset in-kernel each run)
__device__ int g_cnt[5];
__device__ int g_done[5];

__device__ __forceinline__ int ld_acquire_gpu(const int* p)
{
    int v;
    asm volatile("ld.acquire.gpu.global.b32 %0, [%1];" : "=r"(v) : "l"(p) : "memory");
    return v;
}

// ---------------------------------------------------------------------------
// Fused kernel: 40 blocks (k = bx>>3, chunk = bx&7), 256 threads.
// Phase1: gather + Conv1 + BN + ReLU for 32 hidden units -> g_r, then arrive.
// Phase2 (same block, after spin-wait on its level): 8 outputs x 4 batches.
// All 40 blocks co-resident (<<148 SMs) -> spin barrier is deadlock-free.
// ---------------------------------------------------------------------------
__global__ __launch_bounds__(256, 1)
void proj_fused_kernel(const float* __restrict__ x0,
                       const float* __restrict__ x1,
                       const float* __restrict__ x2,
                       const float* __restrict__ x3,
                       const float* __restrict__ x4,
                       const int*   __restrict__ p,
                       const float* __restrict__ w1,
                       const float* __restrict__ b1,
                       const float* __restrict__ gamma,
                       const float* __restrict__ beta,
                       const float* __restrict__ w2,
                       const float* __restrict__ b2,
                       float*       __restrict__ out)
{
    const int k   = blockIdx.x >> 3;       // level 0..4
    const int ch8 = blockIdx.x & 7;        // chunk within level
    const int t   = threadIdx.x;
    const int s   = t & 7;                 // interleaved float4 slot
    const int j   = ch8 * 32 + (t >> 3);   // hidden unit (phase1)

    __shared__ float f_s[BSZ][CH];

    // ================= PHASE 1 =================
    // prefetch w1 + BN params (independent of the p-dependent gather chain)
    const float4* wrow = (const float4*)(w1 + ((long long)k * HID + j) * CH);
    float4 wv[4];
    #pragma unroll
    for (int i = 0; i < 4; ++i)
        wv[i] = wrow[s + 8 * i];

    const float bias = b1[k * HID + j];
    const float gam  = gamma[k * HID + j];
    const float bet  = beta[k * HID + j];

    const float* xs;
    switch (k) {
        case 0: xs = x0; break;
        case 1: xs = x1; break;
        case 2: xs = x2; break;
        case 3: xs = x3; break;
        default: xs = x4; break;
    }
    const int shift = k + 1;
    const int side  = 128 >> shift;

    #pragma unroll
    for (int i = t; i < BSZ * CH; i += 256) {
        const int b = i >> 7;
        const int c = i & (CH - 1);
        const int q0 = p[b * 3 + 0] >> shift;
        const int q1 = p[b * 3 + 1] >> shift;
        const int q2 = p[b * 3 + 2] >> shift;
        const long long idx =
            ((((long long)(b * CH + c) * side + q0) * side + q1) * side + q2);
        f_s[b][c] = xs[idx];
    }
    __syncthreads();

    const float4* f0 = (const float4*)f_s[0];
    const float4* f1 = (const float4*)f_s[1];
    const float4* f2 = (const float4*)f_s[2];
    const float4* f3 = (const float4*)f_s[3];

    float a0 = 0.f, a1 = 0.f, a2 = 0.f, a3 = 0.f;
    #pragma unroll
    for (int i = 0; i < 4; ++i) {
        const int fi = s + 8 * i;
        const float4 w = wv[i];
        float4 v;
        v = f0[fi]; a0 += v.x*w.x + v.y*w.y + v.z*w.z + v.w*w.w;
        v = f1[fi]; a1 += v.x*w.x + v.y*w.y + v.z*w.z + v.w*w.w;
        v = f2[fi]; a2 += v.x*w.x + v.y*w.y + v.z*w.z + v.w*w.w;
        v = f3[fi]; a3 += v.x*w.x + v.y*w.y + v.z*w.z + v.w*w.w;
    }
    #pragma unroll
    for (int m = 1; m < 8; m <<= 1) {
        a0 += __shfl_xor_sync(ALLM, a0, m);
        a1 += __shfl_xor_sync(ALLM, a1, m);
        a2 += __shfl_xor_sync(ALLM, a2, m);
        a3 += __shfl_xor_sync(ALLM, a3, m);
    }

    a0 += bias; a1 += bias; a2 += bias; a3 += bias;
    const float mean = 0.25f * (a0 + a1 + a2 + a3);
    const float d0 = a0 - mean, d1 = a1 - mean, d2 = a2 - mean, d3 = a3 - mean;
    const float var = 0.25f * (d0*d0 + d1*d1 + d2*d2 + d3*d3);
    const float scl = gam * rsqrtf(var + EPSV);

    if (s < 4) {
        const float d = (s == 0) ? d0 : (s == 1) ? d1 : (s == 2) ? d2 : d3;
        g_r[((long long)k * BSZ + s) * HID + j] = fmaxf(d * scl + bet, 0.f);
    }

    // ---- arrive: all 32 r-values of this block are globally visible ----
    __syncthreads();
    if (t == 0) {
        __threadfence();                       // release g_r writes
        atomicAdd(&g_cnt[k], 1);
    }

    // ================= PHASE 2 =================
    // this block handles outputs och*8..och*8+7 of its own level
    const int T = t >> 3;                      // 0..31
    const int b = T & 3;
    const int o = ch8 * 8 + (T >> 2);

    // prefetch w2 (independent of r) to overlap the spin-wait
    const float4* w2row = (const float4*)(w2 + ((long long)k * OUTD + o) * HID);
    float4 wv2[8];
    #pragma unroll
    for (int i = 0; i < 8; ++i)
        wv2[i] = w2row[s + 8 * i];
    const float bias2 = b2[k * OUTD + o];

    // spin until all 8 producer blocks of this level arrived
    if (t == 0) {
        while (ld_acquire_gpu(&g_cnt[k]) != 8) { }
    }
    __syncthreads();                           // broadcast readiness + acquire order

    const float4* rrow = (const float4*)(g_r + ((long long)k * BSZ + b) * HID);
    float acc = 0.f;
    #pragma unroll
    for (int i = 0; i < 8; ++i) {
        const float4 w = wv2[i];
        const float4 r = rrow[s + 8 * i];
        acc += r.x*w.x + r.y*w.y + r.z*w.z + r.w*w.w;
    }
    #pragma unroll
    for (int m = 1; m < 8; m <<= 1)
        acc += __shfl_xor_sync(ALLM, acc, m);

    if (s == 0)
        out[((long long)k * BSZ + b) * OUTD + o] = acc + bias2;

    // ---- reset counters for next graph replay (last block per level) ----
    __syncthreads();
    if (t == 0) {
        const int prev = atomicAdd(&g_done[k], 1);
        if (prev == 7) {                       // last phase2 block of this level
            g_done[k] = 0;
            g_cnt[k]  = 0;
        }
    }
}

extern "C" void kernel_launch(void* const* d_in, const int* in_sizes, int n_in,
                              void* d_out, int out_size)
{
    (void)in_sizes; (void)n_in; (void)out_size;
    const float* x0    = (const float*)d_in[0];
    const float* x1    = (const float*)d_in[1];
    const float* x2    = (const float*)d_in[2];
    const float* x3    = (const float*)d_in[3];
    const float* x4    = (const float*)d_in[4];
    const int*   p     = (const int*)  d_in[5];
    const float* w1    = (const float*)d_in[6];
    const float* b1    = (const float*)d_in[7];
    const float* gamma = (const float*)d_in[8];
    const float* beta  = (const float*)d_in[9];
    const float* w2    = (const float*)d_in[10];
    const float* b2    = (const float*)d_in[11];
    float* out = (float*)d_out;

    proj_fused_kernel<<<40, 256>>>(x0, x1, x2, x3, x4, p,
                                   w1, b1, gamma, beta, w2, b2, out);
}